// round 3
// baseline (speedup 1.0000x reference)
#include <cuda_runtime.h>
#include <math.h>

#define TOK   8192          // B*T
#define EMBD  1024
#define SEQ   2048
#define NHEAD 16
#define HDIM  64
#define SP    65            // padded smem row stride (floats)

// Scratch (allocation-free rule: device globals)
__device__ float g_qkv[(size_t)TOK * 3 * EMBD];   // [tok][3*1024]
__device__ float g_ctx[(size_t)TOK * EMBD];       // [tok][h*64+d]

// ---------------------------------------------------------------------------
// Generic GEMM + bias: C[M,N] = A[M,K] @ B[K,N] + bias[N]
// M fixed = gridDim.y*64 (=8192). Tile 64x64x16, 256 threads, 4x4 per thread.
// ---------------------------------------------------------------------------
__global__ __launch_bounds__(256) void gemm_bias(
    const float* __restrict__ A, const float* __restrict__ B,
    const float* __restrict__ bias, float* __restrict__ C,
    int N, int K)
{
    __shared__ float As[16][64];   // [k][m]
    __shared__ float Bs[16][64];   // [k][n]

    const int tid = threadIdx.x;
    const int tx  = tid & 15;      // col group (4 cols)
    const int ty  = tid >> 4;      // row group (4 rows)
    const int m0  = blockIdx.y * 64;
    const int n0  = blockIdx.x * 64;

    const int ma = tid >> 2;            // A-load row (0..63)
    const int ka = (tid & 3) * 4;       // A-load k   (0..12)
    const int kb = tid >> 4;            // B-load k   (0..15)
    const int nb = (tid & 15) * 4;      // B-load n   (0..60)

    float acc[4][4] = {};

    for (int k0 = 0; k0 < K; k0 += 16) {
        const float4 av = *(const float4*)(A + (size_t)(m0 + ma) * K + k0 + ka);
        const float4 bv = *(const float4*)(B + (size_t)(k0 + kb) * N + n0 + nb);
        __syncthreads();
        As[ka + 0][ma] = av.x; As[ka + 1][ma] = av.y;
        As[ka + 2][ma] = av.z; As[ka + 3][ma] = av.w;
        *(float4*)&Bs[kb][nb] = bv;
        __syncthreads();

        #pragma unroll
        for (int k = 0; k < 16; ++k) {
            const float4 a4 = *(const float4*)&As[k][ty * 4];
            const float4 b4 = *(const float4*)&Bs[k][tx * 4];
            const float a[4] = {a4.x, a4.y, a4.z, a4.w};
            const float b[4] = {b4.x, b4.y, b4.z, b4.w};
            #pragma unroll
            for (int i = 0; i < 4; ++i)
                #pragma unroll
                for (int j = 0; j < 4; ++j)
                    acc[i][j] = fmaf(a[i], b[j], acc[i][j]);
        }
    }

    #pragma unroll
    for (int i = 0; i < 4; ++i) {
        const int row = m0 + ty * 4 + i;
        #pragma unroll
        for (int j = 0; j < 4; ++j) {
            const int col = n0 + tx * 4 + j;
            C[(size_t)row * N + col] = acc[i][j] + bias[col];
        }
    }
}

// ---------------------------------------------------------------------------
// Flash attention (fp32, causal). One block = (64 queries, head h, batch b).
// 128 threads: rg = tid>>3 (4 rows each), cg = tid&7 (8 cols/dims each).
// qkv row layout per token: [q(1024) | k(1024) | v(1024)], head h at h*64.
// ---------------------------------------------------------------------------
__global__ __launch_bounds__(128) void flash_attn(
    const float* __restrict__ qkv, float* __restrict__ ctx)
{
    extern __shared__ float sm[];
    float* Qs  = sm;                 // [64][SP]
    float* Ks  = Qs + 64 * SP;       // [64][SP]
    float* Vs  = Ks + 64 * SP;       // [64][SP]
    float* Ss  = Vs + 64 * SP;       // [64][SP]
    float* m_s = Ss + 64 * SP;       // [64]
    float* l_s = m_s + 64;           // [64]
    float* a_s = l_s + 64;           // [64]

    const int qt  = blockIdx.x;          // query tile 0..31
    const int h   = blockIdx.y;
    const int b   = blockIdx.z;
    const int tid = threadIdx.x;
    const int rg  = tid >> 3;            // 0..15 -> rows 4*rg..
    const int cg  = tid & 7;             // 0..7  -> cols 8*cg..
    const int q0  = qt * 64;

    const int lr  = tid >> 1;            // loader row 0..63
    const int ld0 = (tid & 1) * 32;      // loader dim offset

    // Load Q tile, pre-scaled by HDIM^-0.5 = 0.125
    {
        const float* src = qkv + (size_t)(b * SEQ + q0 + lr) * 3072 + h * HDIM + ld0;
        #pragma unroll
        for (int i = 0; i < 32; i += 4) {
            const float4 v = *(const float4*)(src + i);
            Qs[lr * SP + ld0 + i + 0] = v.x * 0.125f;
            Qs[lr * SP + ld0 + i + 1] = v.y * 0.125f;
            Qs[lr * SP + ld0 + i + 2] = v.z * 0.125f;
            Qs[lr * SP + ld0 + i + 3] = v.w * 0.125f;
        }
    }
    if (tid < 64) { m_s[tid] = -INFINITY; l_s[tid] = 0.f; }

    float O[4][8];
    #pragma unroll
    for (int i = 0; i < 4; ++i)
        #pragma unroll
        for (int j = 0; j < 8; ++j) O[i][j] = 0.f;

    for (int kt = 0; kt <= qt; ++kt) {
        __syncthreads();  // previous PV done with Ks/Vs/Ss; Q/init ready (kt==0)

        // Load K and V tiles
        {
            const float* kp = qkv + (size_t)(b * SEQ + kt * 64 + lr) * 3072
                              + EMBD + h * HDIM + ld0;
            #pragma unroll
            for (int i = 0; i < 32; i += 4) {
                const float4 kv4 = *(const float4*)(kp + i);
                const float4 vv4 = *(const float4*)(kp + EMBD + i);
                Ks[lr * SP + ld0 + i + 0] = kv4.x;
                Ks[lr * SP + ld0 + i + 1] = kv4.y;
                Ks[lr * SP + ld0 + i + 2] = kv4.z;
                Ks[lr * SP + ld0 + i + 3] = kv4.w;
                Vs[lr * SP + ld0 + i + 0] = vv4.x;
                Vs[lr * SP + ld0 + i + 1] = vv4.y;
                Vs[lr * SP + ld0 + i + 2] = vv4.z;
                Vs[lr * SP + ld0 + i + 3] = vv4.w;
            }
        }
        __syncthreads();

        // S = Q @ K^T  (4x8 fragment per thread)
        float s[4][8] = {};
        #pragma unroll 8
        for (int k = 0; k < 64; ++k) {
            float qv[4], kv[8];
            #pragma unroll
            for (int i = 0; i < 4; ++i) qv[i] = Qs[(4 * rg + i) * SP + k];
            #pragma unroll
            for (int j = 0; j < 8; ++j) kv[j] = Ks[(8 * cg + j) * SP + k];
            #pragma unroll
            for (int i = 0; i < 4; ++i)
                #pragma unroll
                for (int j = 0; j < 8; ++j)
                    s[i][j] = fmaf(qv[i], kv[j], s[i][j]);
        }
        const bool diag = (kt == qt);
        #pragma unroll
        for (int i = 0; i < 4; ++i)
            #pragma unroll
            for (int j = 0; j < 8; ++j) {
                float v = s[i][j];
                if (diag && (8 * cg + j) > (4 * rg + i)) v = -INFINITY;
                Ss[(4 * rg + i) * SP + 8 * cg + j] = v;
            }
        __syncthreads();

        // Online softmax: 2 threads per row (lane pair via shfl_xor 1)
        {
            const int r  = lr;
            const int h2 = tid & 1;
            float sv[32];
            float mloc = -INFINITY;
            #pragma unroll
            for (int c = 0; c < 32; ++c) {
                sv[c] = Ss[r * SP + h2 * 32 + c];
                mloc  = fmaxf(mloc, sv[c]);
            }
            mloc = fmaxf(mloc, __shfl_xor_sync(0xffffffffu, mloc, 1));
            const float m_old = m_s[r];
            const float m_new = fmaxf(m_old, mloc);
            float sum = 0.f;
            #pragma unroll
            for (int c = 0; c < 32; ++c) {
                const float p = __expf(sv[c] - m_new);
                sum += p;
                Ss[r * SP + h2 * 32 + c] = p;
            }
            sum += __shfl_xor_sync(0xffffffffu, sum, 1);  // warp-sync: orders m_s write below
            if (h2 == 0) {
                const float alpha = __expf(m_old - m_new);
                m_s[r] = m_new;
                l_s[r] = l_s[r] * alpha + sum;
                a_s[r] = alpha;
            }
        }
        __syncthreads();

        // Rescale O, then O += P @ V
        float al[4];
        #pragma unroll
        for (int i = 0; i < 4; ++i) al[i] = a_s[4 * rg + i];
        #pragma unroll
        for (int i = 0; i < 4; ++i)
            #pragma unroll
            for (int j = 0; j < 8; ++j) O[i][j] *= al[i];

        #pragma unroll 8
        for (int k2 = 0; k2 < 64; ++k2) {
            float pv[4], vv[8];
            #pragma unroll
            for (int i = 0; i < 4; ++i) pv[i] = Ss[(4 * rg + i) * SP + k2];
            #pragma unroll
            for (int j = 0; j < 8; ++j) vv[j] = Vs[k2 * SP + 8 * cg + j];
            #pragma unroll
            for (int i = 0; i < 4; ++i)
                #pragma unroll
                for (int j = 0; j < 8; ++j)
                    O[i][j] = fmaf(pv[i], vv[j], O[i][j]);
        }
    }

    __syncthreads();
    float li[4];
    #pragma unroll
    for (int i = 0; i < 4; ++i) li[i] = 1.0f / l_s[4 * rg + i];
    #pragma unroll
    for (int i = 0; i < 4; ++i) {
        const size_t row = (size_t)(b * SEQ + q0 + 4 * rg + i);
        #pragma unroll
        for (int j = 0; j < 8; ++j)
            ctx[row * EMBD + h * HDIM + 8 * cg + j] = O[i][j] * li[i];
    }
}

// ---------------------------------------------------------------------------
extern "C" void kernel_launch(void* const* d_in, const int* in_sizes, int n_in,
                              void* d_out, int out_size)
{
    const float* x     = (const float*)d_in[0];
    const float* w_qkv = (const float*)d_in[1];
    const float* b_qkv = (const float*)d_in[2];
    const float* w_out = (const float*)d_in[3];
    const float* b_out = (const float*)d_in[4];
    float* out = (float*)d_out;

    float* qkv; cudaGetSymbolAddress((void**)&qkv, g_qkv);
    float* ctx; cudaGetSymbolAddress((void**)&ctx, g_ctx);

    const size_t flash_smem = (size_t)(4 * 64 * SP + 3 * 64) * sizeof(float); // 67,328 B
    cudaFuncSetAttribute(flash_attn, cudaFuncAttributeMaxDynamicSharedMemorySize,
                         (int)flash_smem);

    // 1) qkv = x @ w_qkv + b_qkv      [8192,1024] @ [1024,3072]
    gemm_bias<<<dim3(3072 / 64, TOK / 64), 256>>>(x, w_qkv, b_qkv, qkv, 3072, 1024);
    // 2) causal flash attention -> ctx [tok][h*64+d]
    flash_attn<<<dim3(SEQ / 64, NHEAD, 4), 128, flash_smem>>>(qkv, ctx);
    // 3) out = ctx @ w_out + b_out    [8192,1024] @ [1024,1024]
    gemm_bias<<<dim3(EMBD / 64, TOK / 64), 256>>>(ctx, w_out, b_out, out, 1024, 1024);
}

// round 6
// speedup vs baseline: 1.4562x; 1.4562x over previous
#include <cuda_runtime.h>
#include <cuda_bf16.h>
#include <cstdint>
#include <math.h>

#define TOK   8192
#define EMBD  1024
#define SEQ   2048
#define NHEAD 16
#define HDIM  64
#define SP    65

// ---------------- scratch (allocation-free rule: device globals) ----------
__device__ float g_qkv[(size_t)TOK * 3 * EMBD];
__device__ float g_ctx[(size_t)TOK * EMBD];
__device__ __nv_bfloat16 g_xh[(size_t)TOK * EMBD];
__device__ __nv_bfloat16 g_xl[(size_t)TOK * EMBD];
__device__ __nv_bfloat16 g_ch[(size_t)TOK * EMBD];
__device__ __nv_bfloat16 g_cl[(size_t)TOK * EMBD];
__device__ __nv_bfloat16 g_wqh[(size_t)3 * EMBD * EMBD];
__device__ __nv_bfloat16 g_wql[(size_t)3 * EMBD * EMBD];
__device__ __nv_bfloat16 g_woh[(size_t)EMBD * EMBD];
__device__ __nv_bfloat16 g_wol[(size_t)EMBD * EMBD];

// ---------------- helpers ---------------------------------------------
__device__ __forceinline__ uint32_t smem_u32(const void* p) {
    uint32_t a;
    asm("{ .reg .u64 t; cvta.to.shared.u64 t, %1; cvt.u32.u64 %0, t; }" : "=r"(a) : "l"(p));
    return a;
}

#define LDSM4(r, a) \
    asm volatile("ldmatrix.sync.aligned.m8n8.x4.shared.b16 {%0,%1,%2,%3}, [%4];" \
        : "=r"((r)[0]), "=r"((r)[1]), "=r"((r)[2]), "=r"((r)[3]) : "r"(a))

#define MMA_BF16(c, a, b0, b1) \
    asm volatile("mma.sync.aligned.m16n8k16.row.col.f32.bf16.bf16.f32 " \
        "{%0,%1,%2,%3},{%4,%5,%6,%7},{%8,%9},{%0,%1,%2,%3};" \
        : "+f"((c)[0]), "+f"((c)[1]), "+f"((c)[2]), "+f"((c)[3]) \
        : "r"((a)[0]), "r"((a)[1]), "r"((a)[2]), "r"((a)[3]), "r"(b0), "r"(b1))

#define CP_ASYNC16(so, gp) \
    asm volatile("cp.async.cg.shared.global [%0], [%1], 16;" :: "r"(so), "l"(gp) : "memory")
#define CP_COMMIT() asm volatile("cp.async.commit_group;" ::: "memory")

// ---------------------------------------------------------------------------
// mma.sync bf16 GEMM with Markidis split:
//   C[M,N] = (Ah+Al)[M,1024] @ (Bh+Bl)[N,1024]^T + bias  (3-term: HH + HL + LH)
// Block 128x128, K-slab 32, 8 warps (64x32 each), 2-stage cp.async pipeline.
// Smem row stride 80B (32 bf16 + 8 pad) -> conflict-free ldmatrix.
// ---------------------------------------------------------------------------
#define LDB    80
#define TILEB  (128 * LDB)      // 10240 B
#define GSTAGE (4 * TILEB)      // 40960 B
#define GSMEM  (2 * GSTAGE)     // 81920 B

__global__ __launch_bounds__(256) void gemm_mma(
    const __nv_bfloat16* __restrict__ Ah, const __nv_bfloat16* __restrict__ Al,
    const __nv_bfloat16* __restrict__ Bh, const __nv_bfloat16* __restrict__ Bl,
    const float* __restrict__ bias, float* __restrict__ C, int N)
{
    extern __shared__ char smem[];
    const uint32_t sbase = smem_u32(smem);
    const int tid = threadIdx.x;
    const int wid = tid >> 5;
    const int l   = tid & 31;
    const int m0  = blockIdx.y * 128;
    const int n0  = blockIdx.x * 128;
    const int wm  = (wid >> 2) * 64;     // warp m offset (0/64)
    const int wn  = (wid & 3) * 32;      // warp n offset (0..96)

    const __nv_bfloat16* srcs[4] = {
        Ah + (size_t)m0 * 1024, Al + (size_t)m0 * 1024,
        Bh + (size_t)n0 * 1024, Bl + (size_t)n0 * 1024 };
    const int lrow = tid >> 2;           // 0..63
    const int lseg = tid & 3;            // 16B segment

    // ldmatrix per-lane addressing (shared by A and B tiles)
    const int frow = (l & 7) + ((l >> 3) & 1) * 8;
    const int fkb  = (l >> 4) * 16;      // k8 halves byte offset

    float acc[4][4][4];
    #pragma unroll
    for (int a = 0; a < 4; ++a)
        #pragma unroll
        for (int b = 0; b < 4; ++b)
            #pragma unroll
            for (int c = 0; c < 4; ++c) acc[a][b][c] = 0.f;

    // ---- stage loader (cp.async, 8 x 16B per thread) ----
    auto load_stage = [&](int ks, int buf) {
        const uint32_t sb = sbase + buf * GSTAGE;
        const int kc = ks * 32;
        #pragma unroll
        for (int t = 0; t < 4; ++t) {
            const __nv_bfloat16* s = srcs[t] + kc + lseg * 8;
            #pragma unroll
            for (int j = 0; j < 2; ++j) {
                const int row = lrow + j * 64;
                const uint32_t so = sb + t * TILEB + row * LDB + lseg * 16;
                CP_ASYNC16(so, s + (size_t)row * 1024);
            }
        }
    };

    load_stage(0, 0);
    CP_COMMIT();

    for (int ks = 0; ks < 32; ++ks) {
        const int buf = ks & 1;
        if (ks + 1 < 32) {
            load_stage(ks + 1, buf ^ 1);
            CP_COMMIT();
            asm volatile("cp.async.wait_group 1;" ::: "memory");
        } else {
            asm volatile("cp.async.wait_group 0;" ::: "memory");
        }
        __syncthreads();

        const uint32_t sb = sbase + buf * GSTAGE;
        #pragma unroll
        for (int kk = 0; kk < 2; ++kk) {            // two k16 steps
            const uint32_t kbo = kk * 32 + fkb;
            uint32_t ah[4][4], al_[4][4], bh[2][4], bl_[2][4];
            #pragma unroll
            for (int mt = 0; mt < 4; ++mt) {
                const uint32_t addr = sb + (wm + mt * 16 + frow) * LDB + kbo;
                LDSM4(ah[mt], addr);
                LDSM4(al_[mt], addr + TILEB);
            }
            #pragma unroll
            for (int p = 0; p < 2; ++p) {
                const uint32_t addr = sb + 2 * TILEB + (wn + p * 16 + frow) * LDB + kbo;
                LDSM4(bh[p], addr);
                LDSM4(bl_[p], addr + TILEB);
            }
            #pragma unroll
            for (int mt = 0; mt < 4; ++mt)
                #pragma unroll
                for (int nt = 0; nt < 4; ++nt) {
                    const int p = nt >> 1, o = nt & 1;
                    MMA_BF16(acc[mt][nt], ah[mt],  bh[p][0 + o],  bh[p][2 + o]);
                    MMA_BF16(acc[mt][nt], ah[mt],  bl_[p][0 + o], bl_[p][2 + o]);
                    MMA_BF16(acc[mt][nt], al_[mt], bh[p][0 + o],  bh[p][2 + o]);
                }
        }
        __syncthreads();
    }

    // ---- epilogue: C = acc + bias ----
    const int er = l >> 2, ec = (l & 3) * 2;
    #pragma unroll
    for (int mt = 0; mt < 4; ++mt) {
        #pragma unroll
        for (int nt = 0; nt < 4; ++nt) {
            const int m = m0 + wm + mt * 16 + er;
            const int n = n0 + wn + nt * 8 + ec;
            const float b0 = __ldg(bias + n), b1 = __ldg(bias + n + 1);
            float2 v0 = { acc[mt][nt][0] + b0, acc[mt][nt][1] + b1 };
            float2 v1 = { acc[mt][nt][2] + b0, acc[mt][nt][3] + b1 };
            *(float2*)(C + (size_t)m * N + n)       = v0;
            *(float2*)(C + (size_t)(m + 8) * N + n) = v1;
        }
    }
}

// ---------------------------------------------------------------------------
// prep: fp32 -> (hi, lo) bf16 split, elementwise (vectorized by 4)
// ---------------------------------------------------------------------------
static __device__ __forceinline__ unsigned pack2(float a, float b) {
    __nv_bfloat162 t = __floats2bfloat162_rn(a, b);
    return *reinterpret_cast<unsigned*>(&t);
}
__global__ __launch_bounds__(256) void split_pair(
    const float4* __restrict__ src, uint2* __restrict__ h, uint2* __restrict__ l, int n4)
{
    const int i = blockIdx.x * 256 + threadIdx.x;
    if (i >= n4) return;
    const float4 v = src[i];
    const float hx = __bfloat162float(__float2bfloat16(v.x));
    const float hy = __bfloat162float(__float2bfloat16(v.y));
    const float hz = __bfloat162float(__float2bfloat16(v.z));
    const float hw = __bfloat162float(__float2bfloat16(v.w));
    h[i] = make_uint2(pack2(v.x, v.y), pack2(v.z, v.w));
    l[i] = make_uint2(pack2(v.x - hx, v.y - hy), pack2(v.z - hz, v.w - hw));
}

// prep: W[K,N] fp32 -> Wt_hi/lo [N,K] bf16 (transpose + split)
__global__ void transpose_split(const float* __restrict__ W,
                                __nv_bfloat16* __restrict__ Th,
                                __nv_bfloat16* __restrict__ Tl, int K, int N)
{
    __shared__ float t[32][33];
    const int k0 = blockIdx.y * 32, n0 = blockIdx.x * 32;
    const int x = threadIdx.x, y = threadIdx.y;
    #pragma unroll
    for (int i = 0; i < 32; i += 8)
        t[y + i][x] = W[(size_t)(k0 + y + i) * N + n0 + x];
    __syncthreads();
    #pragma unroll
    for (int i = 0; i < 32; i += 8) {
        const float v = t[x][y + i];
        const __nv_bfloat16 hv = __float2bfloat16(v);
        const size_t o = (size_t)(n0 + y + i) * K + k0 + x;
        Th[o] = hv;
        Tl[o] = __float2bfloat16(v - __bfloat162float(hv));
    }
}

// ---------------------------------------------------------------------------
// Flash attention (fp32, causal) — unchanged from passing R1 kernel
// ---------------------------------------------------------------------------
__global__ __launch_bounds__(128) void flash_attn(
    const float* __restrict__ qkv, float* __restrict__ ctx)
{
    extern __shared__ float sm[];
    float* Qs  = sm;
    float* Ks  = Qs + 64 * SP;
    float* Vs  = Ks + 64 * SP;
    float* Ss  = Vs + 64 * SP;
    float* m_s = Ss + 64 * SP;
    float* l_s = m_s + 64;
    float* a_s = l_s + 64;

    const int qt  = blockIdx.x;
    const int h   = blockIdx.y;
    const int b   = blockIdx.z;
    const int tid = threadIdx.x;
    const int rg  = tid >> 3;
    const int cg  = tid & 7;
    const int q0  = qt * 64;
    const int lr  = tid >> 1;
    const int ld0 = (tid & 1) * 32;

    {
        const float* src = qkv + (size_t)(b * SEQ + q0 + lr) * 3072 + h * HDIM + ld0;
        #pragma unroll
        for (int i = 0; i < 32; i += 4) {
            const float4 v = *(const float4*)(src + i);
            Qs[lr * SP + ld0 + i + 0] = v.x * 0.125f;
            Qs[lr * SP + ld0 + i + 1] = v.y * 0.125f;
            Qs[lr * SP + ld0 + i + 2] = v.z * 0.125f;
            Qs[lr * SP + ld0 + i + 3] = v.w * 0.125f;
        }
    }
    if (tid < 64) { m_s[tid] = -INFINITY; l_s[tid] = 0.f; }

    float O[4][8];
    #pragma unroll
    for (int i = 0; i < 4; ++i)
        #pragma unroll
        for (int j = 0; j < 8; ++j) O[i][j] = 0.f;

    for (int kt = 0; kt <= qt; ++kt) {
        __syncthreads();
        {
            const float* kp = qkv + (size_t)(b * SEQ + kt * 64 + lr) * 3072
                              + EMBD + h * HDIM + ld0;
            #pragma unroll
            for (int i = 0; i < 32; i += 4) {
                const float4 kv4 = *(const float4*)(kp + i);
                const float4 vv4 = *(const float4*)(kp + EMBD + i);
                Ks[lr * SP + ld0 + i + 0] = kv4.x;
                Ks[lr * SP + ld0 + i + 1] = kv4.y;
                Ks[lr * SP + ld0 + i + 2] = kv4.z;
                Ks[lr * SP + ld0 + i + 3] = kv4.w;
                Vs[lr * SP + ld0 + i + 0] = vv4.x;
                Vs[lr * SP + ld0 + i + 1] = vv4.y;
                Vs[lr * SP + ld0 + i + 2] = vv4.z;
                Vs[lr * SP + ld0 + i + 3] = vv4.w;
            }
        }
        __syncthreads();

        float s[4][8] = {};
        #pragma unroll 8
        for (int k = 0; k < 64; ++k) {
            float qv[4], kv[8];
            #pragma unroll
            for (int i = 0; i < 4; ++i) qv[i] = Qs[(4 * rg + i) * SP + k];
            #pragma unroll
            for (int j = 0; j < 8; ++j) kv[j] = Ks[(8 * cg + j) * SP + k];
            #pragma unroll
            for (int i = 0; i < 4; ++i)
                #pragma unroll
                for (int j = 0; j < 8; ++j)
                    s[i][j] = fmaf(qv[i], kv[j], s[i][j]);
        }
        const bool diag = (kt == qt);
        #pragma unroll
        for (int i = 0; i < 4; ++i)
            #pragma unroll
            for (int j = 0; j < 8; ++j) {
                float v = s[i][j];
                if (diag && (8 * cg + j) > (4 * rg + i)) v = -INFINITY;
                Ss[(4 * rg + i) * SP + 8 * cg + j] = v;
            }
        __syncthreads();

        {
            const int r  = lr;
            const int h2 = tid & 1;
            float sv[32];
            float mloc = -INFINITY;
            #pragma unroll
            for (int c = 0; c < 32; ++c) {
                sv[c] = Ss[r * SP + h2 * 32 + c];
                mloc  = fmaxf(mloc, sv[c]);
            }
            mloc = fmaxf(mloc, __shfl_xor_sync(0xffffffffu, mloc, 1));
            const float m_old = m_s[r];
            const float m_new = fmaxf(m_old, mloc);
            float sum = 0.f;
            #pragma unroll
            for (int c = 0; c < 32; ++c) {
                const float p = __expf(sv[c] - m_new);
                sum += p;
                Ss[r * SP + h2 * 32 + c] = p;
            }
            sum += __shfl_xor_sync(0xffffffffu, sum, 1);
            if (h2 == 0) {
                const float alpha = __expf(m_old - m_new);
                m_s[r] = m_new;
                l_s[r] = l_s[r] * alpha + sum;
                a_s[r] = alpha;
            }
        }
        __syncthreads();

        float al[4];
        #pragma unroll
        for (int i = 0; i < 4; ++i) al[i] = a_s[4 * rg + i];
        #pragma unroll
        for (int i = 0; i < 4; ++i)
            #pragma unroll
            for (int j = 0; j < 8; ++j) O[i][j] *= al[i];

        #pragma unroll 8
        for (int k2 = 0; k2 < 64; ++k2) {
            float pv[4], vv[8];
            #pragma unroll
            for (int i = 0; i < 4; ++i) pv[i] = Ss[(4 * rg + i) * SP + k2];
            #pragma unroll
            for (int j = 0; j < 8; ++j) vv[j] = Vs[k2 * SP + 8 * cg + j];
            #pragma unroll
            for (int i = 0; i < 4; ++i)
                #pragma unroll
                for (int j = 0; j < 8; ++j)
                    O[i][j] = fmaf(pv[i], vv[j], O[i][j]);
        }
    }

    __syncthreads();
    float li[4];
    #pragma unroll
    for (int i = 0; i < 4; ++i) li[i] = 1.0f / l_s[4 * rg + i];
    #pragma unroll
    for (int i = 0; i < 4; ++i) {
        const size_t row = (size_t)(b * SEQ + q0 + 4 * rg + i);
        #pragma unroll
        for (int j = 0; j < 8; ++j)
            ctx[row * EMBD + h * HDIM + 8 * cg + j] = O[i][j] * li[i];
    }
}

// ---------------------------------------------------------------------------
extern "C" void kernel_launch(void* const* d_in, const int* in_sizes, int n_in,
                              void* d_out, int out_size)
{
    const float* x     = (const float*)d_in[0];
    const float* w_qkv = (const float*)d_in[1];
    const float* b_qkv = (const float*)d_in[2];
    const float* w_out = (const float*)d_in[3];
    const float* b_out = (const float*)d_in[4];
    float* out = (float*)d_out;

    float *qkv, *ctx;
    __nv_bfloat16 *xh, *xl, *ch, *cl, *wqh, *wql, *woh, *wol;
    cudaGetSymbolAddress((void**)&qkv, g_qkv);
    cudaGetSymbolAddress((void**)&ctx, g_ctx);
    cudaGetSymbolAddress((void**)&xh, g_xh);
    cudaGetSymbolAddress((void**)&xl, g_xl);
    cudaGetSymbolAddress((void**)&ch, g_ch);
    cudaGetSymbolAddress((void**)&cl, g_cl);
    cudaGetSymbolAddress((void**)&wqh, g_wqh);
    cudaGetSymbolAddress((void**)&wql, g_wql);
    cudaGetSymbolAddress((void**)&woh, g_woh);
    cudaGetSymbolAddress((void**)&wol, g_wol);

    const size_t flash_smem = (size_t)(4 * 64 * SP + 3 * 64) * sizeof(float);
    cudaFuncSetAttribute(flash_attn, cudaFuncAttributeMaxDynamicSharedMemorySize,
                         (int)flash_smem);
    cudaFuncSetAttribute(gemm_mma, cudaFuncAttributeMaxDynamicSharedMemorySize, GSMEM);

    const int n4 = TOK * EMBD / 4;

    // prep: split x, transpose+split weights
    split_pair<<<n4 / 256, 256>>>((const float4*)x, (uint2*)xh, (uint2*)xl, n4);
    transpose_split<<<dim3(3 * EMBD / 32, EMBD / 32), dim3(32, 8)>>>(w_qkv, wqh, wql, EMBD, 3 * EMBD);
    transpose_split<<<dim3(EMBD / 32, EMBD / 32), dim3(32, 8)>>>(w_out, woh, wol, EMBD, EMBD);

    // 1) qkv = x @ w_qkv + b_qkv   (mma.sync split-bf16)
    gemm_mma<<<dim3(3 * EMBD / 128, TOK / 128), 256, GSMEM>>>(xh, xl, wqh, wql, b_qkv, qkv, 3 * EMBD);
    // 2) causal flash attention
    flash_attn<<<dim3(SEQ / 64, NHEAD, 4), 128, flash_smem>>>(qkv, ctx);
    // 3) split ctx, then out = ctx @ w_out + b_out
    split_pair<<<n4 / 256, 256>>>((const float4*)ctx, (uint2*)ch, (uint2*)cl, n4);
    gemm_mma<<<dim3(EMBD / 128, TOK / 128), 256, GSMEM>>>(ch, cl, woh, wol, b_out, out, EMBD);
}

// round 7
// speedup vs baseline: 2.3744x; 1.6306x over previous
#include <cuda_runtime.h>
#include <cuda_bf16.h>
#include <cstdint>
#include <math.h>

#define TOK   8192
#define EMBD  1024
#define SEQ   2048
#define NHEAD 16
#define HDIM  64

// ---------------- scratch (allocation-free rule: device globals) ----------
__device__ float g_qkv[(size_t)TOK * 3 * EMBD];
__device__ float g_ctx[(size_t)TOK * EMBD];
__device__ __nv_bfloat16 g_xh[(size_t)TOK * EMBD];
__device__ __nv_bfloat16 g_xl[(size_t)TOK * EMBD];
__device__ __nv_bfloat16 g_ch[(size_t)TOK * EMBD];
__device__ __nv_bfloat16 g_cl[(size_t)TOK * EMBD];
__device__ __nv_bfloat16 g_wqh[(size_t)3 * EMBD * EMBD];
__device__ __nv_bfloat16 g_wql[(size_t)3 * EMBD * EMBD];
__device__ __nv_bfloat16 g_woh[(size_t)EMBD * EMBD];
__device__ __nv_bfloat16 g_wol[(size_t)EMBD * EMBD];

// ---------------- helpers ---------------------------------------------
__device__ __forceinline__ uint32_t smem_u32(const void* p) {
    uint32_t a;
    asm("{ .reg .u64 t; cvta.to.shared.u64 t, %1; cvt.u32.u64 %0, t; }" : "=r"(a) : "l"(p));
    return a;
}

#define LDSM4(r, a) \
    asm volatile("ldmatrix.sync.aligned.m8n8.x4.shared.b16 {%0,%1,%2,%3}, [%4];" \
        : "=r"((r)[0]), "=r"((r)[1]), "=r"((r)[2]), "=r"((r)[3]) : "r"(a))

#define MMA_BF16(c, a, b0, b1) \
    asm volatile("mma.sync.aligned.m16n8k16.row.col.f32.bf16.bf16.f32 " \
        "{%0,%1,%2,%3},{%4,%5,%6,%7},{%8,%9},{%0,%1,%2,%3};" \
        : "+f"((c)[0]), "+f"((c)[1]), "+f"((c)[2]), "+f"((c)[3]) \
        : "r"((a)[0]), "r"((a)[1]), "r"((a)[2]), "r"((a)[3]), "r"(b0), "r"(b1))

#define CP_ASYNC16(so, gp) \
    asm volatile("cp.async.cg.shared.global [%0], [%1], 16;" :: "r"(so), "l"(gp) : "memory")
#define CP_COMMIT() asm volatile("cp.async.commit_group;" ::: "memory")

// fast exp2 on fma pipe (arg <= 0, clamped), rel err ~2e-5
__device__ __forceinline__ float exp2f_fast(float t) {
    t = fmaxf(t, -100.0f);
    float fi = floorf(t);
    float f  = t - fi;
    float p  = 1.33335581e-3f;
    p = fmaf(p, f, 9.61812910e-3f);
    p = fmaf(p, f, 5.55041087e-2f);
    p = fmaf(p, f, 2.40226507e-1f);
    p = fmaf(p, f, 6.93147182e-1f);
    p = fmaf(p, f, 1.0f);
    return __int_as_float(((int)fi + 127) << 23) * p;
}

// split x,y into bf16x2 hi + bf16x2 lo residual
__device__ __forceinline__ void split2(float x, float y, uint32_t& hi, uint32_t& lo) {
    __nv_bfloat162 h2 = __floats2bfloat162_rn(x, y);
    float2 hf = __bfloat1622float2(h2);
    __nv_bfloat162 l2 = __floats2bfloat162_rn(x - hf.x, y - hf.y);
    hi = *reinterpret_cast<uint32_t*>(&h2);
    lo = *reinterpret_cast<uint32_t*>(&l2);
}

// ---------------------------------------------------------------------------
// mma.sync bf16 GEMM with Markidis split (unchanged from R6, passing)
// ---------------------------------------------------------------------------
#define LDB    80
#define TILEB  (128 * LDB)
#define GSTAGE (4 * TILEB)
#define GSMEM  (2 * GSTAGE)

__global__ __launch_bounds__(256) void gemm_mma(
    const __nv_bfloat16* __restrict__ Ah, const __nv_bfloat16* __restrict__ Al,
    const __nv_bfloat16* __restrict__ Bh, const __nv_bfloat16* __restrict__ Bl,
    const float* __restrict__ bias, float* __restrict__ C, int N)
{
    extern __shared__ char smem[];
    const uint32_t sbase = smem_u32(smem);
    const int tid = threadIdx.x;
    const int wid = tid >> 5;
    const int l   = tid & 31;
    const int m0  = blockIdx.y * 128;
    const int n0  = blockIdx.x * 128;
    const int wm  = (wid >> 2) * 64;
    const int wn  = (wid & 3) * 32;

    const __nv_bfloat16* srcs[4] = {
        Ah + (size_t)m0 * 1024, Al + (size_t)m0 * 1024,
        Bh + (size_t)n0 * 1024, Bl + (size_t)n0 * 1024 };
    const int lrow = tid >> 2;
    const int lseg = tid & 3;

    const int frow = (l & 7) + ((l >> 3) & 1) * 8;
    const int fkb  = (l >> 4) * 16;

    float acc[4][4][4];
    #pragma unroll
    for (int a = 0; a < 4; ++a)
        #pragma unroll
        for (int b = 0; b < 4; ++b)
            #pragma unroll
            for (int c = 0; c < 4; ++c) acc[a][b][c] = 0.f;

    auto load_stage = [&](int ks, int buf) {
        const uint32_t sb = sbase + buf * GSTAGE;
        const int kc = ks * 32;
        #pragma unroll
        for (int t = 0; t < 4; ++t) {
            const __nv_bfloat16* s = srcs[t] + kc + lseg * 8;
            #pragma unroll
            for (int j = 0; j < 2; ++j) {
                const int row = lrow + j * 64;
                const uint32_t so = sb + t * TILEB + row * LDB + lseg * 16;
                CP_ASYNC16(so, s + (size_t)row * 1024);
            }
        }
    };

    load_stage(0, 0);
    CP_COMMIT();

    for (int ks = 0; ks < 32; ++ks) {
        const int buf = ks & 1;
        if (ks + 1 < 32) {
            load_stage(ks + 1, buf ^ 1);
            CP_COMMIT();
            asm volatile("cp.async.wait_group 1;" ::: "memory");
        } else {
            asm volatile("cp.async.wait_group 0;" ::: "memory");
        }
        __syncthreads();

        const uint32_t sb = sbase + buf * GSTAGE;
        #pragma unroll
        for (int kk = 0; kk < 2; ++kk) {
            const uint32_t kbo = kk * 32 + fkb;
            uint32_t ah[4][4], al_[4][4], bh[2][4], bl_[2][4];
            #pragma unroll
            for (int mt = 0; mt < 4; ++mt) {
                const uint32_t addr = sb + (wm + mt * 16 + frow) * LDB + kbo;
                LDSM4(ah[mt], addr);
                LDSM4(al_[mt], addr + TILEB);
            }
            #pragma unroll
            for (int p = 0; p < 2; ++p) {
                const uint32_t addr = sb + 2 * TILEB + (wn + p * 16 + frow) * LDB + kbo;
                LDSM4(bh[p], addr);
                LDSM4(bl_[p], addr + TILEB);
            }
            #pragma unroll
            for (int mt = 0; mt < 4; ++mt)
                #pragma unroll
                for (int nt = 0; nt < 4; ++nt) {
                    const int p = nt >> 1, o = nt & 1;
                    MMA_BF16(acc[mt][nt], ah[mt],  bh[p][0 + o],  bh[p][2 + o]);
                    MMA_BF16(acc[mt][nt], ah[mt],  bl_[p][0 + o], bl_[p][2 + o]);
                    MMA_BF16(acc[mt][nt], al_[mt], bh[p][0 + o],  bh[p][2 + o]);
                }
        }
        __syncthreads();
    }

    const int er = l >> 2, ec = (l & 3) * 2;
    #pragma unroll
    for (int mt = 0; mt < 4; ++mt) {
        #pragma unroll
        for (int nt = 0; nt < 4; ++nt) {
            const int m = m0 + wm + mt * 16 + er;
            const int n = n0 + wn + nt * 8 + ec;
            const float b0 = __ldg(bias + n), b1 = __ldg(bias + n + 1);
            float2 v0 = { acc[mt][nt][0] + b0, acc[mt][nt][1] + b1 };
            float2 v1 = { acc[mt][nt][2] + b0, acc[mt][nt][3] + b1 };
            *(float2*)(C + (size_t)m * N + n)       = v0;
            *(float2*)(C + (size_t)(m + 8) * N + n) = v1;
        }
    }
}

// ---------------------------------------------------------------------------
// HMMA flash attention (split-bf16 3-term QK^T and PV, causal, fp32 softmax)
// Block: 64 queries x (head, batch). 4 warps, 16 query rows per warp.
// Smem: Qh Ql Kh Kl Vth Vtl, each [64][72] bf16 (144B rows, conflict-free LDSM).
// ---------------------------------------------------------------------------
#define AST   72                  // bf16 elements per smem row
#define ASTB  (AST * 2)           // 144 bytes
#define ATILE (64 * ASTB)         // 9216 bytes per tile
#define ASMEM (6 * ATILE)         // 55296 bytes

__global__ __launch_bounds__(128) void attn_mma(
    const float* __restrict__ qkv, float* __restrict__ ctx)
{
    extern __shared__ char smem[];
    const uint32_t sQh = smem_u32(smem);
    const uint32_t sQl = sQh + ATILE;
    const uint32_t sKh = sQh + 2 * ATILE;
    const uint32_t sKl = sQh + 3 * ATILE;
    const uint32_t sVh = sQh + 4 * ATILE;
    const uint32_t sVl = sQh + 5 * ATILE;
    __nv_bfloat16* bsm = (__nv_bfloat16*)smem;

    const int qt  = blockIdx.x;
    const int h   = blockIdx.y;
    const int b   = blockIdx.z;
    const int tid = threadIdx.x;
    const int w   = tid >> 5;
    const int l   = tid & 31;
    const int q0  = qt * 64;

    const int lr  = tid >> 1;          // loader row 0..63
    const int ld0 = (tid & 1) * 32;    // loader dim offset

    const int frow = (l & 7) + ((l >> 3) & 1) * 8;
    const int fkb  = (l >> 4) * 16;

    // ---- load Q tile (pre-scaled by 0.125 * log2(e)), split hi/lo ----
    const float QSC = 0.1803368801111244f;
    {
        const float* src = qkv + (size_t)(b * SEQ + q0 + lr) * 3072 + h * HDIM + ld0;
        #pragma unroll
        for (int i = 0; i < 32; i += 4) {
            const float4 v = *(const float4*)(src + i);
            uint32_t h0, l0, h1, l1;
            split2(v.x * QSC, v.y * QSC, h0, l0);
            split2(v.z * QSC, v.w * QSC, h1, l1);
            const int o = lr * AST + ld0 + i;
            *(uint32_t*)(bsm + o)                   = h0;
            *(uint32_t*)(bsm + o + 2)               = h1;
            *(uint32_t*)(bsm + (ATILE / 2) + o)     = l0;
            *(uint32_t*)(bsm + (ATILE / 2) + o + 2) = l1;
        }
    }
    __syncthreads();

    float o_[8][4];
    #pragma unroll
    for (int nt = 0; nt < 8; ++nt)
        #pragma unroll
        for (int c = 0; c < 4; ++c) o_[nt][c] = 0.f;
    float mA = -1e30f, mB = -1e30f, lA = 0.f, lB = 0.f;

    const int rA = w * 16 + (l >> 2);     // in-tile query row (c0,c1)
    const int cBase = (l & 3) * 2;        // in-tile col base within 8-tile

    for (int kt = 0; kt <= qt; ++kt) {
        // ---- load K,V tiles, split hi/lo; V transposed -> [dim][kpos] ----
        {
            const float* kp_ = qkv + (size_t)(b * SEQ + kt * 64 + lr) * 3072
                               + EMBD + h * HDIM + ld0;
            __nv_bfloat16* kh = bsm + ATILE + lr * AST + ld0;          // sKh
            __nv_bfloat16* kl = kh + (ATILE / 2);
            __nv_bfloat16* vh = bsm + 2 * ATILE + lr;                  // sVh col
            __nv_bfloat16* vl = vh + (ATILE / 2);
            #pragma unroll
            for (int i = 0; i < 32; i += 4) {
                const float4 kv4 = *(const float4*)(kp_ + i);
                const float4 vv4 = *(const float4*)(kp_ + EMBD + i);
                uint32_t h0, l0, h1, l1;
                split2(kv4.x, kv4.y, h0, l0);
                split2(kv4.z, kv4.w, h1, l1);
                *(uint32_t*)(kh + i)                = h0;
                *(uint32_t*)(kh + i + 2)            = h1;
                *(uint32_t*)(kl + i)                = l0;
                *(uint32_t*)(kl + i + 2)            = l1;
                const float vs[4] = {vv4.x, vv4.y, vv4.z, vv4.w};
                #pragma unroll
                for (int j = 0; j < 4; ++j) {
                    const __nv_bfloat16 hv = __float2bfloat16(vs[j]);
                    vh[(ld0 + i + j) * AST] = hv;
                    vl[(ld0 + i + j) * AST] =
                        __float2bfloat16(vs[j] - __bfloat162float(hv));
                }
            }
        }
        __syncthreads();

        // ---- S = Q K^T (3-term split), S in log2 units ----
        float s[8][4];
        #pragma unroll
        for (int nt = 0; nt < 8; ++nt)
            #pragma unroll
            for (int c = 0; c < 4; ++c) s[nt][c] = 0.f;

        #pragma unroll
        for (int kk = 0; kk < 4; ++kk) {
            const uint32_t kbo = kk * 32 + fkb;
            uint32_t qh[4], ql[4], kh[4][4], kl[4][4];
            {
                const uint32_t qa = sQh + (w * 16 + frow) * ASTB + kbo;
                LDSM4(qh, qa);
                LDSM4(ql, qa + ATILE);
            }
            #pragma unroll
            for (int p = 0; p < 4; ++p) {
                const uint32_t ka = sKh + (p * 16 + frow) * ASTB + kbo;
                LDSM4(kh[p], ka);
                LDSM4(kl[p], ka + ATILE);
            }
            #pragma unroll
            for (int nt = 0; nt < 8; ++nt) {
                const int p = nt >> 1, o = nt & 1;
                MMA_BF16(s[nt], qh, kh[p][0 + o], kh[p][2 + o]);
                MMA_BF16(s[nt], qh, kl[p][0 + o], kl[p][2 + o]);
                MMA_BF16(s[nt], ql, kh[p][0 + o], kh[p][2 + o]);
            }
        }

        // ---- causal mask (diagonal tile only) ----
        if (kt == qt) {
            #pragma unroll
            for (int nt = 0; nt < 8; ++nt) {
                const int c0 = nt * 8 + cBase;
                if (c0 > rA)     s[nt][0] = -1e30f;
                if (c0 + 1 > rA) s[nt][1] = -1e30f;
                if (c0 > rA + 8)     s[nt][2] = -1e30f;
                if (c0 + 1 > rA + 8) s[nt][3] = -1e30f;
            }
        }

        // ---- online softmax (registers + quad shfl) ----
        float mlA = -1e30f, mlB = -1e30f;
        #pragma unroll
        for (int nt = 0; nt < 8; ++nt) {
            mlA = fmaxf(mlA, fmaxf(s[nt][0], s[nt][1]));
            mlB = fmaxf(mlB, fmaxf(s[nt][2], s[nt][3]));
        }
        mlA = fmaxf(mlA, __shfl_xor_sync(0xffffffffu, mlA, 1));
        mlA = fmaxf(mlA, __shfl_xor_sync(0xffffffffu, mlA, 2));
        mlB = fmaxf(mlB, __shfl_xor_sync(0xffffffffu, mlB, 1));
        mlB = fmaxf(mlB, __shfl_xor_sync(0xffffffffu, mlB, 2));
        const float mAn = fmaxf(mA, mlA);
        const float mBn = fmaxf(mB, mlB);
        const float aAl = exp2f_fast(mA - mAn);
        const float aBl = exp2f_fast(mB - mBn);
        mA = mAn; mB = mBn;

        float sumA = 0.f, sumB = 0.f;
        #pragma unroll
        for (int nt = 0; nt < 8; ++nt) {
            s[nt][0] = exp2f_fast(s[nt][0] - mAn);
            s[nt][1] = exp2f_fast(s[nt][1] - mAn);
            s[nt][2] = exp2f_fast(s[nt][2] - mBn);
            s[nt][3] = exp2f_fast(s[nt][3] - mBn);
            sumA += s[nt][0] + s[nt][1];
            sumB += s[nt][2] + s[nt][3];
        }
        sumA += __shfl_xor_sync(0xffffffffu, sumA, 1);
        sumA += __shfl_xor_sync(0xffffffffu, sumA, 2);
        sumB += __shfl_xor_sync(0xffffffffu, sumB, 1);
        sumB += __shfl_xor_sync(0xffffffffu, sumB, 2);
        lA = lA * aAl + sumA;
        lB = lB * aBl + sumB;

        #pragma unroll
        for (int nt = 0; nt < 8; ++nt) {
            o_[nt][0] *= aAl; o_[nt][1] *= aAl;
            o_[nt][2] *= aBl; o_[nt][3] *= aBl;
        }

        // ---- O += P V (3-term split); P from S fragments ----
        #pragma unroll
        for (int kp = 0; kp < 4; ++kp) {
            uint32_t pha[4], pla[4];
            split2(s[2 * kp][0],     s[2 * kp][1],     pha[0], pla[0]);
            split2(s[2 * kp][2],     s[2 * kp][3],     pha[1], pla[1]);
            split2(s[2 * kp + 1][0], s[2 * kp + 1][1], pha[2], pla[2]);
            split2(s[2 * kp + 1][2], s[2 * kp + 1][3], pha[3], pla[3]);

            const uint32_t kbo = kp * 32 + fkb;
            uint32_t vh[4][4], vl[4][4];
            #pragma unroll
            for (int p = 0; p < 4; ++p) {
                const uint32_t va = sVh + (p * 16 + frow) * ASTB + kbo;
                LDSM4(vh[p], va);
                LDSM4(vl[p], va + ATILE);
            }
            #pragma unroll
            for (int nt = 0; nt < 8; ++nt) {
                const int p = nt >> 1, o = nt & 1;
                MMA_BF16(o_[nt], pha, vh[p][0 + o], vh[p][2 + o]);
                MMA_BF16(o_[nt], pha, vl[p][0 + o], vl[p][2 + o]);
                MMA_BF16(o_[nt], pla, vh[p][0 + o], vh[p][2 + o]);
            }
        }
        __syncthreads();   // all smem reads done before next tile's stores
    }

    // ---- epilogue: normalize and write ctx ----
    const float iA = 1.0f / lA, iB = 1.0f / lB;
    const size_t row0 = (size_t)(b * SEQ + q0 + rA);
    #pragma unroll
    for (int nt = 0; nt < 8; ++nt) {
        const int d = h * HDIM + nt * 8 + cBase;
        float2 v0 = { o_[nt][0] * iA, o_[nt][1] * iA };
        float2 v1 = { o_[nt][2] * iB, o_[nt][3] * iB };
        *(float2*)(ctx + row0 * EMBD + d)       = v0;
        *(float2*)(ctx + (row0 + 8) * EMBD + d) = v1;
    }
}

// ---------------------------------------------------------------------------
// prep kernels (unchanged)
// ---------------------------------------------------------------------------
static __device__ __forceinline__ unsigned pack2(float a, float b) {
    __nv_bfloat162 t = __floats2bfloat162_rn(a, b);
    return *reinterpret_cast<unsigned*>(&t);
}
__global__ __launch_bounds__(256) void split_pair(
    const float4* __restrict__ src, uint2* __restrict__ h, uint2* __restrict__ l, int n4)
{
    const int i = blockIdx.x * 256 + threadIdx.x;
    if (i >= n4) return;
    const float4 v = src[i];
    const float hx = __bfloat162float(__float2bfloat16(v.x));
    const float hy = __bfloat162float(__float2bfloat16(v.y));
    const float hz = __bfloat162float(__float2bfloat16(v.z));
    const float hw = __bfloat162float(__float2bfloat16(v.w));
    h[i] = make_uint2(pack2(v.x, v.y), pack2(v.z, v.w));
    l[i] = make_uint2(pack2(v.x - hx, v.y - hy), pack2(v.z - hz, v.w - hw));
}

__global__ void transpose_split(const float* __restrict__ W,
                                __nv_bfloat16* __restrict__ Th,
                                __nv_bfloat16* __restrict__ Tl, int K, int N)
{
    __shared__ float t[32][33];
    const int k0 = blockIdx.y * 32, n0 = blockIdx.x * 32;
    const int x = threadIdx.x, y = threadIdx.y;
    #pragma unroll
    for (int i = 0; i < 32; i += 8)
        t[y + i][x] = W[(size_t)(k0 + y + i) * N + n0 + x];
    __syncthreads();
    #pragma unroll
    for (int i = 0; i < 32; i += 8) {
        const float v = t[x][y + i];
        const __nv_bfloat16 hv = __float2bfloat16(v);
        const size_t o = (size_t)(n0 + y + i) * K + k0 + x;
        Th[o] = hv;
        Tl[o] = __float2bfloat16(v - __bfloat162float(hv));
    }
}

// ---------------------------------------------------------------------------
extern "C" void kernel_launch(void* const* d_in, const int* in_sizes, int n_in,
                              void* d_out, int out_size)
{
    const float* x     = (const float*)d_in[0];
    const float* w_qkv = (const float*)d_in[1];
    const float* b_qkv = (const float*)d_in[2];
    const float* w_out = (const float*)d_in[3];
    const float* b_out = (const float*)d_in[4];
    float* out = (float*)d_out;

    float *qkv, *ctx;
    __nv_bfloat16 *xh, *xl, *ch, *cl, *wqh, *wql, *woh, *wol;
    cudaGetSymbolAddress((void**)&qkv, g_qkv);
    cudaGetSymbolAddress((void**)&ctx, g_ctx);
    cudaGetSymbolAddress((void**)&xh, g_xh);
    cudaGetSymbolAddress((void**)&xl, g_xl);
    cudaGetSymbolAddress((void**)&ch, g_ch);
    cudaGetSymbolAddress((void**)&cl, g_cl);
    cudaGetSymbolAddress((void**)&wqh, g_wqh);
    cudaGetSymbolAddress((void**)&wql, g_wql);
    cudaGetSymbolAddress((void**)&woh, g_woh);
    cudaGetSymbolAddress((void**)&wol, g_wol);

    cudaFuncSetAttribute(gemm_mma, cudaFuncAttributeMaxDynamicSharedMemorySize, GSMEM);
    cudaFuncSetAttribute(attn_mma, cudaFuncAttributeMaxDynamicSharedMemorySize, ASMEM);

    const int n4 = TOK * EMBD / 4;

    split_pair<<<n4 / 256, 256>>>((const float4*)x, (uint2*)xh, (uint2*)xl, n4);
    transpose_split<<<dim3(3 * EMBD / 32, EMBD / 32), dim3(32, 8)>>>(w_qkv, wqh, wql, EMBD, 3 * EMBD);
    transpose_split<<<dim3(EMBD / 32, EMBD / 32), dim3(32, 8)>>>(w_out, woh, wol, EMBD, EMBD);

    // 1) qkv = x @ w_qkv + b_qkv
    gemm_mma<<<dim3(3 * EMBD / 128, TOK / 128), 256, GSMEM>>>(xh, xl, wqh, wql, b_qkv, qkv, 3 * EMBD);
    // 2) causal flash attention (HMMA)
    attn_mma<<<dim3(SEQ / 64, NHEAD, 4), 128, ASMEM>>>(qkv, ctx);
    // 3) out = ctx @ w_out + b_out
    split_pair<<<n4 / 256, 256>>>((const float4*)ctx, (uint2*)ch, (uint2*)cl, n4);
    gemm_mma<<<dim3(EMBD / 128, TOK / 128), 256, GSMEM>>>(ch, cl, woh, wol, b_out, out, EMBD);
}

// round 9
// speedup vs baseline: 3.0245x; 1.2738x over previous
#include <cuda_runtime.h>
#include <cuda_bf16.h>
#include <cstdint>
#include <math.h>

#define TOK   8192
#define EMBD  1024
#define SEQ   2048
#define NHEAD 16
#define HDIM  64

// ---------------- scratch (allocation-free rule: device globals) ----------
__device__ float g_qkv[(size_t)TOK * 3 * EMBD];
__device__ __nv_bfloat16 g_xh[(size_t)TOK * EMBD];
__device__ __nv_bfloat16 g_xl[(size_t)TOK * EMBD];
__device__ __nv_bfloat16 g_ch[(size_t)TOK * EMBD];
__device__ __nv_bfloat16 g_cl[(size_t)TOK * EMBD];
__device__ __nv_bfloat16 g_wqh[(size_t)3 * EMBD * EMBD];
__device__ __nv_bfloat16 g_wql[(size_t)3 * EMBD * EMBD];
__device__ __nv_bfloat16 g_woh[(size_t)EMBD * EMBD];
__device__ __nv_bfloat16 g_wol[(size_t)EMBD * EMBD];
// attention operands (split bf16, prepped once)
__device__ __nv_bfloat16 g_qsh[(size_t)TOK * EMBD];   // scaled Q  [tok][h*64+d]
__device__ __nv_bfloat16 g_qsl[(size_t)TOK * EMBD];
__device__ __nv_bfloat16 g_ksh[(size_t)TOK * EMBD];   // K         [tok][h*64+d]
__device__ __nv_bfloat16 g_ksl[(size_t)TOK * EMBD];
__device__ __nv_bfloat16 g_vth[(size_t)TOK * EMBD];   // V^T       [b,h,d][t]
__device__ __nv_bfloat16 g_vtl[(size_t)TOK * EMBD];

// ---------------- helpers ---------------------------------------------
__device__ __forceinline__ uint32_t smem_u32(const void* p) {
    uint32_t a;
    asm("{ .reg .u64 t; cvta.to.shared.u64 t, %1; cvt.u32.u64 %0, t; }" : "=r"(a) : "l"(p));
    return a;
}

#define LDSM4(r, a) \
    asm volatile("ldmatrix.sync.aligned.m8n8.x4.shared.b16 {%0,%1,%2,%3}, [%4];" \
        : "=r"((r)[0]), "=r"((r)[1]), "=r"((r)[2]), "=r"((r)[3]) : "r"(a))

#define MMA_BF16(c, a, b0, b1) \
    asm volatile("mma.sync.aligned.m16n8k16.row.col.f32.bf16.bf16.f32 " \
        "{%0,%1,%2,%3},{%4,%5,%6,%7},{%8,%9},{%0,%1,%2,%3};" \
        : "+f"((c)[0]), "+f"((c)[1]), "+f"((c)[2]), "+f"((c)[3]) \
        : "r"((a)[0]), "r"((a)[1]), "r"((a)[2]), "r"((a)[3]), "r"(b0), "r"(b1))

#define CP_ASYNC16(so, gp) \
    asm volatile("cp.async.cg.shared.global [%0], [%1], 16;" :: "r"(so), "l"(gp) : "memory")
#define CP_COMMIT() asm volatile("cp.async.commit_group;" ::: "memory")
#define CP_WAIT0()  asm volatile("cp.async.wait_group 0;" ::: "memory")

// fast exp2 on fma pipe (arg <= 0, clamped), rel err ~2e-5
__device__ __forceinline__ float exp2f_fast(float t) {
    t = fmaxf(t, -100.0f);
    float fi = floorf(t);
    float f  = t - fi;
    float p  = 1.33335581e-3f;
    p = fmaf(p, f, 9.61812910e-3f);
    p = fmaf(p, f, 5.55041087e-2f);
    p = fmaf(p, f, 2.40226507e-1f);
    p = fmaf(p, f, 6.93147182e-1f);
    p = fmaf(p, f, 1.0f);
    return __int_as_float(((int)fi + 127) << 23) * p;
}

__device__ __forceinline__ void split2(float x, float y, uint32_t& hi, uint32_t& lo) {
    __nv_bfloat162 h2 = __floats2bfloat162_rn(x, y);
    float2 hf = __bfloat1622float2(h2);
    __nv_bfloat162 l2 = __floats2bfloat162_rn(x - hf.x, y - hf.y);
    hi = *reinterpret_cast<uint32_t*>(&h2);
    lo = *reinterpret_cast<uint32_t*>(&l2);
}

// ---------------------------------------------------------------------------
// mma.sync bf16 GEMM with Markidis split. Single-sync 2-stage pipeline.
// ---------------------------------------------------------------------------
#define LDB    80
#define TILEB  (128 * LDB)
#define GSTAGE (4 * TILEB)
#define GSMEM  (2 * GSTAGE)

__global__ __launch_bounds__(256) void gemm_mma(
    const __nv_bfloat16* __restrict__ Ah, const __nv_bfloat16* __restrict__ Al,
    const __nv_bfloat16* __restrict__ Bh, const __nv_bfloat16* __restrict__ Bl,
    const float* __restrict__ bias, float* __restrict__ C, int N)
{
    extern __shared__ char smem[];
    const uint32_t sbase = smem_u32(smem);
    const int tid = threadIdx.x;
    const int wid = tid >> 5;
    const int l   = tid & 31;
    const int m0  = blockIdx.y * 128;
    const int n0  = blockIdx.x * 128;
    const int wm  = (wid >> 2) * 64;
    const int wn  = (wid & 3) * 32;

    const __nv_bfloat16* srcs[4] = {
        Ah + (size_t)m0 * 1024, Al + (size_t)m0 * 1024,
        Bh + (size_t)n0 * 1024, Bl + (size_t)n0 * 1024 };
    const int lrow = tid >> 2;
    const int lseg = tid & 3;

    const int frow = (l & 7) + ((l >> 3) & 1) * 8;
    const int fkb  = (l >> 4) * 16;

    float acc[4][4][4];
    #pragma unroll
    for (int a = 0; a < 4; ++a)
        #pragma unroll
        for (int b = 0; b < 4; ++b)
            #pragma unroll
            for (int c = 0; c < 4; ++c) acc[a][b][c] = 0.f;

    auto load_stage = [&](int ks, int buf) {
        const uint32_t sb = sbase + buf * GSTAGE;
        const int kc = ks * 32;
        #pragma unroll
        for (int t = 0; t < 4; ++t) {
            const __nv_bfloat16* s = srcs[t] + kc + lseg * 8;
            #pragma unroll
            for (int j = 0; j < 2; ++j) {
                const int row = lrow + j * 64;
                const uint32_t so = sb + t * TILEB + row * LDB + lseg * 16;
                CP_ASYNC16(so, s + (size_t)row * 1024);
            }
        }
    };

    load_stage(0, 0);
    CP_COMMIT();

    for (int ks = 0; ks < 32; ++ks) {
        const int buf = ks & 1;
        CP_WAIT0();
        __syncthreads();
        if (ks + 1 < 32) { load_stage(ks + 1, buf ^ 1); CP_COMMIT(); }

        const uint32_t sb = sbase + buf * GSTAGE;
        #pragma unroll
        for (int kk = 0; kk < 2; ++kk) {
            const uint32_t kbo = kk * 32 + fkb;
            uint32_t ah[4][4], al_[4][4], bh[2][4], bl_[2][4];
            #pragma unroll
            for (int mt = 0; mt < 4; ++mt) {
                const uint32_t addr = sb + (wm + mt * 16 + frow) * LDB + kbo;
                LDSM4(ah[mt], addr);
                LDSM4(al_[mt], addr + TILEB);
            }
            #pragma unroll
            for (int p = 0; p < 2; ++p) {
                const uint32_t addr = sb + 2 * TILEB + (wn + p * 16 + frow) * LDB + kbo;
                LDSM4(bh[p], addr);
                LDSM4(bl_[p], addr + TILEB);
            }
            #pragma unroll
            for (int mt = 0; mt < 4; ++mt)
                #pragma unroll
                for (int nt = 0; nt < 4; ++nt) {
                    const int p = nt >> 1, o = nt & 1;
                    MMA_BF16(acc[mt][nt], ah[mt],  bh[p][0 + o],  bh[p][2 + o]);
                    MMA_BF16(acc[mt][nt], ah[mt],  bl_[p][0 + o], bl_[p][2 + o]);
                    MMA_BF16(acc[mt][nt], al_[mt], bh[p][0 + o],  bh[p][2 + o]);
                }
        }
    }

    __syncthreads();
    const int er = l >> 2, ec = (l & 3) * 2;
    #pragma unroll
    for (int mt = 0; mt < 4; ++mt) {
        #pragma unroll
        for (int nt = 0; nt < 4; ++nt) {
            const int m = m0 + wm + mt * 16 + er;
            const int n = n0 + wn + nt * 8 + ec;
            const float b0 = __ldg(bias + n), b1 = __ldg(bias + n + 1);
            float2 v0 = { acc[mt][nt][0] + b0, acc[mt][nt][1] + b1 };
            float2 v1 = { acc[mt][nt][2] + b0, acc[mt][nt][3] + b1 };
            *(float2*)(C + (size_t)m * N + n)       = v0;
            *(float2*)(C + (size_t)(m + 8) * N + n) = v1;
        }
    }
}

// ---------------------------------------------------------------------------
// HMMA flash attention v2: operands pre-split in global, pure tensor inner loop.
// Block: 64 q x (h,b); 4 warps x 16 q-rows. Smem tiles 64x64 bf16, 128B rows,
// XOR-swizzled (chunk ^= row&7) for conflict-free cp.async + ldmatrix.
// ---------------------------------------------------------------------------
#define AT    8192                 // one 64x64 bf16 tile
#define ASTG  (4 * AT)             // Kh Kl Vh Vl per stage
#define ASMEM (2 * AT + 2 * ASTG)  // Qh Ql + 2 stages = 81920 B

__global__ __launch_bounds__(128) void attn_mma(
    const __nv_bfloat16* __restrict__ Qh, const __nv_bfloat16* __restrict__ Ql,
    const __nv_bfloat16* __restrict__ Kh, const __nv_bfloat16* __restrict__ Kl,
    const __nv_bfloat16* __restrict__ Vth, const __nv_bfloat16* __restrict__ Vtl,
    __nv_bfloat16* __restrict__ Ch, __nv_bfloat16* __restrict__ Cl)
{
    extern __shared__ char smem[];
    const uint32_t sQ = smem_u32(smem);

    const int qt  = blockIdx.x;
    const int h   = blockIdx.y;
    const int b   = blockIdx.z;
    const int tid = threadIdx.x;
    const int w   = tid >> 5;
    const int l   = tid & 31;
    const int q0  = qt * 64;

    const int lr  = tid >> 1;            // loader row 0..63
    const int lc  = tid & 1;             // chunk group

    const int frow = (l & 7) + ((l >> 3) & 1) * 8;
    const int fch  = l >> 4;             // k16-half chunk bit

    // ---- prologue: Q tiles + stage 0 ----
    {
        const __nv_bfloat16* qs = Qh + (size_t)(b * SEQ + q0 + lr) * EMBD + h * HDIM;
        const __nv_bfloat16* qsl2 = Ql + (size_t)(b * SEQ + q0 + lr) * EMBD + h * HDIM;
        #pragma unroll
        for (int i = 0; i < 4; ++i) {
            const int c = lc * 4 + i;
            const uint32_t o = lr * 128 + ((c ^ (lr & 7)) << 4);
            CP_ASYNC16(sQ + o,      qs + c * 8);
            CP_ASYNC16(sQ + AT + o, qsl2 + c * 8);
        }
    }
    auto load_stage = [&](int kt, int buf) {
        const uint32_t sb = sQ + 2 * AT + buf * ASTG;
        const __nv_bfloat16* ks = Kh + (size_t)(b * SEQ + kt * 64 + lr) * EMBD + h * HDIM;
        const __nv_bfloat16* kls = Kl + (size_t)(b * SEQ + kt * 64 + lr) * EMBD + h * HDIM;
        const __nv_bfloat16* vs = Vth + (size_t)((b * NHEAD + h) * HDIM + lr) * SEQ + kt * 64;
        const __nv_bfloat16* vls = Vtl + (size_t)((b * NHEAD + h) * HDIM + lr) * SEQ + kt * 64;
        #pragma unroll
        for (int i = 0; i < 4; ++i) {
            const int c = lc * 4 + i;
            const uint32_t o = lr * 128 + ((c ^ (lr & 7)) << 4);
            CP_ASYNC16(sb + o,          ks + c * 8);
            CP_ASYNC16(sb + AT + o,     kls + c * 8);
            CP_ASYNC16(sb + 2 * AT + o, vs + c * 8);
            CP_ASYNC16(sb + 3 * AT + o, vls + c * 8);
        }
    };
    load_stage(0, 0);
    CP_COMMIT();

    float o_[8][4];
    #pragma unroll
    for (int nt = 0; nt < 8; ++nt)
        #pragma unroll
        for (int c = 0; c < 4; ++c) o_[nt][c] = 0.f;
    float mA = -1e30f, mB = -1e30f, lA = 0.f, lB = 0.f;

    const int rA = w * 16 + (l >> 2);
    const int cBase = (l & 3) * 2;

    for (int kt = 0; kt <= qt; ++kt) {
        const int buf = kt & 1;
        CP_WAIT0();
        __syncthreads();
        if (kt < qt) { load_stage(kt + 1, buf ^ 1); CP_COMMIT(); }

        const uint32_t sb = sQ + 2 * AT + buf * ASTG;

        // ---- S = Q K^T (3-term split) ----
        float s[8][4];
        #pragma unroll
        for (int nt = 0; nt < 8; ++nt)
            #pragma unroll
            for (int c = 0; c < 4; ++c) s[nt][c] = 0.f;

        #pragma unroll
        for (int kk = 0; kk < 4; ++kk) {
            const int cI = kk * 2 + fch;
            uint32_t qh[4], ql[4], kh[4][4], kl[4][4];
            {
                const int qr = w * 16 + frow;
                const uint32_t qa = sQ + qr * 128 + ((cI ^ (qr & 7)) << 4);
                LDSM4(qh, qa);
                LDSM4(ql, qa + AT);
            }
            #pragma unroll
            for (int p = 0; p < 4; ++p) {
                const int kr = p * 16 + frow;
                const uint32_t ka = sb + kr * 128 + ((cI ^ (kr & 7)) << 4);
                LDSM4(kh[p], ka);
                LDSM4(kl[p], ka + AT);
            }
            #pragma unroll
            for (int nt = 0; nt < 8; ++nt) {
                const int p = nt >> 1, o = nt & 1;
                MMA_BF16(s[nt], qh, kh[p][0 + o], kh[p][2 + o]);
                MMA_BF16(s[nt], qh, kl[p][0 + o], kl[p][2 + o]);
                MMA_BF16(s[nt], ql, kh[p][0 + o], kh[p][2 + o]);
            }
        }

        if (kt == qt) {
            #pragma unroll
            for (int nt = 0; nt < 8; ++nt) {
                const int c0 = nt * 8 + cBase;
                if (c0 > rA)         s[nt][0] = -1e30f;
                if (c0 + 1 > rA)     s[nt][1] = -1e30f;
                if (c0 > rA + 8)     s[nt][2] = -1e30f;
                if (c0 + 1 > rA + 8) s[nt][3] = -1e30f;
            }
        }

        // ---- online softmax (registers + quad shfl), log2 domain ----
        float mlA = -1e30f, mlB = -1e30f;
        #pragma unroll
        for (int nt = 0; nt < 8; ++nt) {
            mlA = fmaxf(mlA, fmaxf(s[nt][0], s[nt][1]));
            mlB = fmaxf(mlB, fmaxf(s[nt][2], s[nt][3]));
        }
        mlA = fmaxf(mlA, __shfl_xor_sync(0xffffffffu, mlA, 1));
        mlA = fmaxf(mlA, __shfl_xor_sync(0xffffffffu, mlA, 2));
        mlB = fmaxf(mlB, __shfl_xor_sync(0xffffffffu, mlB, 1));
        mlB = fmaxf(mlB, __shfl_xor_sync(0xffffffffu, mlB, 2));
        const float mAn = fmaxf(mA, mlA);
        const float mBn = fmaxf(mB, mlB);
        const float aAl = exp2f_fast(mA - mAn);
        const float aBl = exp2f_fast(mB - mBn);
        mA = mAn; mB = mBn;

        float sumA = 0.f, sumB = 0.f;
        #pragma unroll
        for (int nt = 0; nt < 8; ++nt) {
            s[nt][0] = exp2f_fast(s[nt][0] - mAn);
            s[nt][1] = exp2f_fast(s[nt][1] - mAn);
            s[nt][2] = exp2f_fast(s[nt][2] - mBn);
            s[nt][3] = exp2f_fast(s[nt][3] - mBn);
            sumA += s[nt][0] + s[nt][1];
            sumB += s[nt][2] + s[nt][3];
        }
        sumA += __shfl_xor_sync(0xffffffffu, sumA, 1);
        sumA += __shfl_xor_sync(0xffffffffu, sumA, 2);
        sumB += __shfl_xor_sync(0xffffffffu, sumB, 1);
        sumB += __shfl_xor_sync(0xffffffffu, sumB, 2);
        lA = lA * aAl + sumA;
        lB = lB * aBl + sumB;

        #pragma unroll
        for (int nt = 0; nt < 8; ++nt) {
            o_[nt][0] *= aAl; o_[nt][1] *= aAl;
            o_[nt][2] *= aBl; o_[nt][3] *= aBl;
        }

        // ---- O += P V (3-term split) ----
        #pragma unroll
        for (int kp = 0; kp < 4; ++kp) {
            uint32_t pha[4], pla[4];
            split2(s[2 * kp][0],     s[2 * kp][1],     pha[0], pla[0]);
            split2(s[2 * kp][2],     s[2 * kp][3],     pha[1], pla[1]);
            split2(s[2 * kp + 1][0], s[2 * kp + 1][1], pha[2], pla[2]);
            split2(s[2 * kp + 1][2], s[2 * kp + 1][3], pha[3], pla[3]);

            const int cI = kp * 2 + fch;
            uint32_t vh[4][4], vl[4][4];
            #pragma unroll
            for (int p = 0; p < 4; ++p) {
                const int vr = p * 16 + frow;
                const uint32_t va = sb + 2 * AT + vr * 128 + ((cI ^ (vr & 7)) << 4);
                LDSM4(vh[p], va);
                LDSM4(vl[p], va + AT);
            }
            #pragma unroll
            for (int nt = 0; nt < 8; ++nt) {
                const int p = nt >> 1, o = nt & 1;
                MMA_BF16(o_[nt], pha, vh[p][0 + o], vh[p][2 + o]);
                MMA_BF16(o_[nt], pha, vl[p][0 + o], vl[p][2 + o]);
                MMA_BF16(o_[nt], pla, vh[p][0 + o], vh[p][2 + o]);
            }
        }
    }

    // ---- epilogue: normalize, split to bf16 hi/lo, write ch/cl ----
    const float iA = 1.0f / lA, iB = 1.0f / lB;
    const size_t row0 = (size_t)(b * SEQ + q0 + rA);
    #pragma unroll
    for (int nt = 0; nt < 8; ++nt) {
        const int d = h * HDIM + nt * 8 + cBase;
        uint32_t h0, l0, h1, l1;
        split2(o_[nt][0] * iA, o_[nt][1] * iA, h0, l0);
        split2(o_[nt][2] * iB, o_[nt][3] * iB, h1, l1);
        *(uint32_t*)(Ch + row0 * EMBD + d)       = h0;
        *(uint32_t*)(Cl + row0 * EMBD + d)       = l0;
        *(uint32_t*)(Ch + (row0 + 8) * EMBD + d) = h1;
        *(uint32_t*)(Cl + (row0 + 8) * EMBD + d) = l1;
    }
}

// ---------------------------------------------------------------------------
// prep kernels
// ---------------------------------------------------------------------------
static __device__ __forceinline__ unsigned pack2(float a, float b) {
    __nv_bfloat162 t = __floats2bfloat162_rn(a, b);
    return *reinterpret_cast<unsigned*>(&t);
}
__global__ __launch_bounds__(256) void split_pair(
    const float4* __restrict__ src, uint2* __restrict__ h, uint2* __restrict__ l, int n4)
{
    const int i = blockIdx.x * 256 + threadIdx.x;
    if (i >= n4) return;
    const float4 v = src[i];
    const float hx = __bfloat162float(__float2bfloat16(v.x));
    const float hy = __bfloat162float(__float2bfloat16(v.y));
    const float hz = __bfloat162float(__float2bfloat16(v.z));
    const float hw = __bfloat162float(__float2bfloat16(v.w));
    h[i] = make_uint2(pack2(v.x, v.y), pack2(v.z, v.w));
    l[i] = make_uint2(pack2(v.x - hx, v.y - hy), pack2(v.z - hz, v.w - hw));
}

// split Q (scaled) and K slices of qkv into bf16 hi/lo, layout [tok][1024]
__global__ __launch_bounds__(256) void qk_split(
    const float* __restrict__ qkv,
    uint2* __restrict__ qh, uint2* __restrict__ ql,
    uint2* __restrict__ kh, uint2* __restrict__ kl)
{
    const float QSC = 0.1803368801111244f;   // 0.125 * log2(e)
    const int i = blockIdx.x * 256 + threadIdx.x;   // over TOK*256
    const int tok = i >> 8, c4 = (i & 255);
    {
        const float4 v = *(const float4*)(qkv + (size_t)tok * 3072 + c4 * 4);
        const float x = v.x * QSC, y = v.y * QSC, z = v.z * QSC, w = v.w * QSC;
        const float hx = __bfloat162float(__float2bfloat16(x));
        const float hy = __bfloat162float(__float2bfloat16(y));
        const float hz = __bfloat162float(__float2bfloat16(z));
        const float hw = __bfloat162float(__float2bfloat16(w));
        qh[(size_t)tok * 256 + c4] = make_uint2(pack2(x, y), pack2(z, w));
        ql[(size_t)tok * 256 + c4] = make_uint2(pack2(x - hx, y - hy), pack2(z - hz, w - hw));
    }
    {
        const float4 v = *(const float4*)(qkv + (size_t)tok * 3072 + 1024 + c4 * 4);
        const float hx = __bfloat162float(__float2bfloat16(v.x));
        const float hy = __bfloat162float(__float2bfloat16(v.y));
        const float hz = __bfloat162float(__float2bfloat16(v.z));
        const float hw = __bfloat162float(__float2bfloat16(v.w));
        kh[(size_t)tok * 256 + c4] = make_uint2(pack2(v.x, v.y), pack2(v.z, v.w));
        kl[(size_t)tok * 256 + c4] = make_uint2(pack2(v.x - hx, v.y - hy), pack2(v.z - hz, v.w - hw));
    }
}

// V slice of qkv -> transposed split [b,h,d][t]
__global__ void vt_split(const float* __restrict__ qkv,
                         __nv_bfloat16* __restrict__ Th,
                         __nv_bfloat16* __restrict__ Tl)
{
    __shared__ float t[32][33];
    const int t0 = blockIdx.x * 32;           // token tile
    const int d0 = blockIdx.y * 32;           // dim-in-head tile (0/32)
    const int bh = blockIdx.z;                // b*16+h
    const int b  = bh >> 4, h = bh & 15;
    const int x = threadIdx.x, y = threadIdx.y;
    #pragma unroll
    for (int i = 0; i < 32; i += 8)
        t[y + i][x] = qkv[(size_t)(b * SEQ + t0 + y + i) * 3072 + 2048 + h * HDIM + d0 + x];
    __syncthreads();
    #pragma unroll
    for (int i = 0; i < 32; i += 8) {
        const float v = t[x][y + i];
        const __nv_bfloat16 hv = __float2bfloat16(v);
        const size_t o = (size_t)(bh * HDIM + d0 + y + i) * SEQ + t0 + x;
        Th[o] = hv;
        Tl[o] = __float2bfloat16(v - __bfloat162float(hv));
    }
}

__global__ void transpose_split(const float* __restrict__ W,
                                __nv_bfloat16* __restrict__ Th,
                                __nv_bfloat16* __restrict__ Tl, int K, int N)
{
    __shared__ float t[32][33];
    const int k0 = blockIdx.y * 32, n0 = blockIdx.x * 32;
    const int x = threadIdx.x, y = threadIdx.y;
    #pragma unroll
    for (int i = 0; i < 32; i += 8)
        t[y + i][x] = W[(size_t)(k0 + y + i) * N + n0 + x];
    __syncthreads();
    #pragma unroll
    for (int i = 0; i < 32; i += 8) {
        const float v = t[x][y + i];
        const __nv_bfloat16 hv = __float2bfloat16(v);
        const size_t o = (size_t)(n0 + y + i) * K + k0 + x;
        Th[o] = hv;
        Tl[o] = __float2bfloat16(v - __bfloat162float(hv));
    }
}

// ---------------------------------------------------------------------------
extern "C" void kernel_launch(void* const* d_in, const int* in_sizes, int n_in,
                              void* d_out, int out_size)
{
    const float* x     = (const float*)d_in[0];
    const float* w_qkv = (const float*)d_in[1];
    const float* b_qkv = (const float*)d_in[2];
    const float* w_out = (const float*)d_in[3];
    const float* b_out = (const float*)d_in[4];
    float* out = (float*)d_out;

    float* qkv;
    __nv_bfloat16 *xh, *xl, *ch, *cl, *wqh, *wql, *woh, *wol;
    __nv_bfloat16 *qsh, *qsl, *ksh, *ksl, *vth, *vtl;
    cudaGetSymbolAddress((void**)&qkv, g_qkv);
    cudaGetSymbolAddress((void**)&xh, g_xh);
    cudaGetSymbolAddress((void**)&xl, g_xl);
    cudaGetSymbolAddress((void**)&ch, g_ch);
    cudaGetSymbolAddress((void**)&cl, g_cl);
    cudaGetSymbolAddress((void**)&wqh, g_wqh);
    cudaGetSymbolAddress((void**)&wql, g_wql);
    cudaGetSymbolAddress((void**)&woh, g_woh);
    cudaGetSymbolAddress((void**)&wol, g_wol);
    cudaGetSymbolAddress((void**)&qsh, g_qsh);
    cudaGetSymbolAddress((void**)&qsl, g_qsl);
    cudaGetSymbolAddress((void**)&ksh, g_ksh);
    cudaGetSymbolAddress((void**)&ksl, g_ksl);
    cudaGetSymbolAddress((void**)&vth, g_vth);
    cudaGetSymbolAddress((void**)&vtl, g_vtl);

    cudaFuncSetAttribute(gemm_mma, cudaFuncAttributeMaxDynamicSharedMemorySize, GSMEM);
    cudaFuncSetAttribute(attn_mma, cudaFuncAttributeMaxDynamicSharedMemorySize, ASMEM);

    const int n4 = TOK * EMBD / 4;

    split_pair<<<n4 / 256, 256>>>((const float4*)x, (uint2*)xh, (uint2*)xl, n4);
    transpose_split<<<dim3(3 * EMBD / 32, EMBD / 32), dim3(32, 8)>>>(w_qkv, wqh, wql, EMBD, 3 * EMBD);
    transpose_split<<<dim3(EMBD / 32, EMBD / 32), dim3(32, 8)>>>(w_out, woh, wol, EMBD, EMBD);

    // 1) qkv = x @ w_qkv + b_qkv
    gemm_mma<<<dim3(3 * EMBD / 128, TOK / 128), 256, GSMEM>>>(xh, xl, wqh, wql, b_qkv, qkv, 3 * EMBD);

    // 2) prep attention operands (split once)
    qk_split<<<TOK, 256>>>(qkv, (uint2*)qsh, (uint2*)qsl, (uint2*)ksh, (uint2*)ksl);
    vt_split<<<dim3(SEQ / 32, HDIM / 32, 4 * NHEAD), dim3(32, 8)>>>(qkv, vth, vtl);

    // 3) causal flash attention (pure HMMA inner loop) -> split ctx
    attn_mma<<<dim3(SEQ / 64, NHEAD, 4), 128, ASMEM>>>(qsh, qsl, ksh, ksl, vth, vtl, ch, cl);

    // 4) out = ctx @ w_out + b_out
    gemm_mma<<<dim3(EMBD / 128, TOK / 128), 256, GSMEM>>>(ch, cl, woh, wol, b_out, out, EMBD);
}